// round 1
// baseline (speedup 1.0000x reference)
#include <cuda_runtime.h>

// ---------------- problem constants ----------------
#define Gn 4
#define Sn 2048
#define Dn 2048
#define En 64
#define NTOK (Gn*Sn)                 // 8192 tokens
#define NCOMB ((long long)NTOK*En*63)// 33,030,144 combine elements
#define SPLITS 4
#define DSUB (Dn/SPLITS)             // 512
#define DC 64                        // K-chunk per smem stage
#define TOKTILE 64
#define K1_THREADS 128
#define K1_BLOCKS ((NTOK/TOKTILE)*SPLITS)  // 128*4 = 512

// ---------------- device scratch (no allocs allowed) ----------------
// partial logits, stored as packed f32x2 pairs for aligned 64-bit stores
__device__ unsigned long long g_part2[(size_t)SPLITS*NTOK*En/2]; // 8 MB
__device__ float2 g_gate[NTOK];
__device__ int2   g_eidx[NTOK];

// ---------------- f32x2 helpers ----------------
__device__ __forceinline__ unsigned long long ffma2(unsigned long long a,
                                                    unsigned long long b,
                                                    unsigned long long c) {
    unsigned long long d;
    asm("fma.rn.f32x2 %0, %1, %2, %3;" : "=l"(d) : "l"(a), "l"(b), "l"(c));
    return d;
}
__device__ __forceinline__ unsigned long long pack2(float x) {
    unsigned long long r;
    asm("mov.b64 %0, {%1, %1};" : "=l"(r) : "r"(__float_as_int(x)));
    return r;
}

// ================= K1: zero-fill output + split-K fp32 GEMM =================
__global__ void __launch_bounds__(K1_THREADS)
k1_zero_gemm(const float* __restrict__ x, const float* __restrict__ W,
             float* __restrict__ out, long long out_n)
{
    // ---- phase A: zero the whole output (overlaps with GEMM via DRAM drain) ----
    {
        long long n4 = out_n >> 2;
        float4 z = make_float4(0.f, 0.f, 0.f, 0.f);
        float4* o4 = (float4*)out;
        long long idx    = (long long)blockIdx.x * K1_THREADS + threadIdx.x;
        long long stride = (long long)gridDim.x * K1_THREADS;
        for (long long i = idx; i < n4; i += stride) o4[i] = z;
        if (blockIdx.x == 0 && threadIdx.x < (int)(out_n & 3LL))
            out[n4*4 + threadIdx.x] = 0.f;
    }

    // ---- phase B: GEMM partial: CTA tile 64 tokens x 64 experts over D-range 512 ----
    __shared__ float xs[TOKTILE][DC + 1];   // natural layout, +1 pad => conflict-free reads
    __shared__ float ws[DC][En];            // natural layout, rows 256B => aligned LDS.128

    const int ct = blockIdx.x % (NTOK/TOKTILE);
    const int sp = blockIdx.x / (NTOK/TOKTILE);
    const int T0 = ct * TOKTILE;
    const int d0 = sp * DSUB;
    const int tid = threadIdx.x;
    const int tg  = tid >> 3;   // 16 token-groups of 4 tokens
    const int eg  = tid & 7;    // 8 expert-groups of 8 experts (4 f32x2 pairs)

    unsigned long long acc[16];
#pragma unroll
    for (int i = 0; i < 16; ++i) acc[i] = 0ull;

    for (int c = 0; c < DSUB/DC; ++c) {
        const int dc0 = d0 + c*DC;
        __syncthreads();
        // fill x tile: coalesced LDG.32, conflict-free STS
        for (int i = tid; i < TOKTILE*DC; i += K1_THREADS) {
            int t = i >> 6, d = i & 63;
            xs[t][d] = x[(size_t)(T0 + t)*Dn + dc0 + d];
        }
        // fill W tile
        for (int i = tid; i < DC*En; i += K1_THREADS) {
            int d = i >> 6, e = i & 63;
            ws[d][e] = W[(size_t)(dc0 + d)*En + e];
        }
        __syncthreads();

#pragma unroll 4
        for (int d = 0; d < DC; ++d) {
            unsigned long long X0 = pack2(xs[4*tg + 0][d]);
            unsigned long long X1 = pack2(xs[4*tg + 1][d]);
            unsigned long long X2 = pack2(xs[4*tg + 2][d]);
            unsigned long long X3 = pack2(xs[4*tg + 3][d]);
            const ulonglong2* wr = (const ulonglong2*)&ws[d][8*eg];
            ulonglong2 wa = wr[0];     // experts (e0,e0+1),(e0+2,e0+3)
            ulonglong2 wb = wr[1];     // experts (e0+4,e0+5),(e0+6,e0+7)
            acc[ 0] = ffma2(X0, wa.x, acc[ 0]);
            acc[ 1] = ffma2(X0, wa.y, acc[ 1]);
            acc[ 2] = ffma2(X0, wb.x, acc[ 2]);
            acc[ 3] = ffma2(X0, wb.y, acc[ 3]);
            acc[ 4] = ffma2(X1, wa.x, acc[ 4]);
            acc[ 5] = ffma2(X1, wa.y, acc[ 5]);
            acc[ 6] = ffma2(X1, wb.x, acc[ 6]);
            acc[ 7] = ffma2(X1, wb.y, acc[ 7]);
            acc[ 8] = ffma2(X2, wa.x, acc[ 8]);
            acc[ 9] = ffma2(X2, wa.y, acc[ 9]);
            acc[10] = ffma2(X2, wb.x, acc[10]);
            acc[11] = ffma2(X2, wb.y, acc[11]);
            acc[12] = ffma2(X3, wa.x, acc[12]);
            acc[13] = ffma2(X3, wa.y, acc[13]);
            acc[14] = ffma2(X3, wb.x, acc[14]);
            acc[15] = ffma2(X3, wb.y, acc[15]);
        }
    }

    // store partials (aligned 64-bit stores of expert pairs)
#pragma unroll
    for (int i = 0; i < 4; ++i) {
        int t = T0 + 4*tg + i;
        unsigned long long* dst =
            g_part2 + ((size_t)sp*NTOK + t)*(En/2) + 4*eg;
#pragma unroll
        for (int j = 0; j < 4; ++j) dst[j] = acc[i*4 + j];
    }
}

// ================= K2: reduce partials + softmax + top-2 =================
#define K2_WARPS 8
__global__ void __launch_bounds__(K2_WARPS*32)
k2_softmax_top2(const float* __restrict__ b)
{
    int t    = blockIdx.x * K2_WARPS + (threadIdx.x >> 5);
    int lane = threadIdx.x & 31;
    if (t >= NTOK) return;

    const float* gp = (const float*)g_part2;
    float l0 = 0.f, l1 = 0.f;
#pragma unroll
    for (int s = 0; s < SPLITS; ++s) {
        const float* p = gp + ((size_t)s*NTOK + t)*En;
        l0 += p[lane];
        l1 += p[lane + 32];
    }
    l0 += b[lane];
    l1 += b[lane + 32];

    // softmax (max-subtract, exp, divide) — mirrors jax.nn.softmax
    float m = fmaxf(l0, l1);
#pragma unroll
    for (int o = 16; o > 0; o >>= 1) m = fmaxf(m, __shfl_xor_sync(0xffffffffu, m, o));
    float p0 = expf(l0 - m), p1 = expf(l1 - m);
    float s = p0 + p1;
#pragma unroll
    for (int o = 16; o > 0; o >>= 1) s += __shfl_xor_sync(0xffffffffu, s, o);
    p0 = p0 / s;
    p1 = p1 / s;

    // top-1 on probs, tie -> lower index (matches lax.top_k)
    float bp; int be;
    if (p1 > p0) { bp = p1; be = lane + 32; } else { bp = p0; be = lane; }
    float wp = bp; int we = be;
#pragma unroll
    for (int o = 16; o > 0; o >>= 1) {
        float op = __shfl_xor_sync(0xffffffffu, wp, o);
        int   oe = __shfl_xor_sync(0xffffffffu, we, o);
        if (op > wp || (op == wp && oe < we)) { wp = op; we = oe; }
    }
    // top-2: exclude winner index
    float a0 = (lane      == we) ? -1.f : p0;
    float a1 = (lane + 32 == we) ? -1.f : p1;
    float bp2; int be2;
    if (a1 > a0) { bp2 = a1; be2 = lane + 32; } else { bp2 = a0; be2 = lane; }
    float wp2 = bp2; int we2 = be2;
#pragma unroll
    for (int o = 16; o > 0; o >>= 1) {
        float op = __shfl_xor_sync(0xffffffffu, wp2, o);
        int   oe = __shfl_xor_sync(0xffffffffu, we2, o);
        if (op > wp2 || (op == wp2 && oe < we2)) { wp2 = op; we2 = oe; }
    }

    if (lane == 0) {
        g_gate[t] = make_float2(wp, wp2);
        g_eidx[t] = make_int2(we, we2);
    }
}

// ================= K3: per-(g,k) scan (cumsum positions) + scatter =================
__global__ void __launch_bounds__(256)
k3_scan_scatter(float* __restrict__ out, long long out_n,
                const int* __restrict__ capp, int has_mask)
{
    __shared__ int cnt[8][En];
    __shared__ unsigned char se[NTOK*2];   // expert index per (token, slot)

    int tid = threadIdx.x;
    int cap = 64;
    if (capp) { cap = capp[0]; if (cap > 64) cap = 64; }

    for (int i = tid; i < NTOK; i += 256) {
        int2 e = g_eidx[i];
        se[2*i + 0] = (unsigned char)e.x;
        se[2*i + 1] = (unsigned char)e.y;
    }
    for (int i = tid; i < 8*En; i += 256) ((int*)cnt)[i] = 0;
    __syncthreads();

    int w = tid >> 5, lane = tid & 31;
    int g = w >> 1, k = w & 1;
    int* mycnt = cnt[w];

    for (int c = 0; c < Sn/32; ++c) {
        int t = g*Sn + c*32 + lane;
        int e = se[2*t + k];
        unsigned mask = __match_any_sync(0xffffffffu, e);
        int rank = __popc(mask & ((1u << lane) - 1u));
        int base = mycnt[e];
        int pos  = base + rank + 1;
        __syncwarp();
        if (rank == 0) mycnt[e] = base + __popc(mask);
        __syncwarp();
        if (pos < cap) {
            float2 gg = g_gate[t];
            float gate = (k == 0) ? gg.x : gg.y;
            long long off = ((long long)t*En + e)*63 + (pos - 1);
            if (off < out_n) out[off] = gate;
            if (has_mask) {
                long long moff = NCOMB + off;
                if (moff < out_n) out[moff] = (gate != 0.f) ? 1.f : 0.f;
            }
        }
    }
}

// ================= launch =================
extern "C" void kernel_launch(void* const* d_in, const int* in_sizes, int n_in,
                              void* d_out, int out_size)
{
    const float* x = (const float*)d_in[0];
    const float* W = (const float*)d_in[1];
    const float* b = (const float*)d_in[2];
    const int* capp = (n_in >= 4) ? (const int*)d_in[3] : nullptr;
    float* out = (float*)d_out;
    long long out_n = (long long)out_size;
    int has_mask = (out_n >= 2LL*NCOMB) ? 1 : 0;

    k1_zero_gemm<<<K1_BLOCKS, K1_THREADS>>>(x, W, out, out_n);
    k2_softmax_top2<<<NTOK/K2_WARPS, K2_WARPS*32>>>(b);
    k3_scan_scatter<<<1, 256>>>(out, out_n, capp, has_mask);
}

// round 2
// speedup vs baseline: 1.1496x; 1.1496x over previous
#include <cuda_runtime.h>

// ---------------- problem constants ----------------
#define Gn 4
#define Sn 2048
#define Dn 2048
#define En 64
#define NTOK (Gn*Sn)                 // 8192 tokens
#define NCOMB ((long long)NTOK*En*63)// 33,030,144 combine elements
#define SPLITS 8
#define DSUB (Dn/SPLITS)             // 256
#define DC 64                        // K-chunk per smem stage
#define TOKTILE 64
#define K1_THREADS 128
#define K1_BLOCKS ((NTOK/TOKTILE)*SPLITS)  // 128*8 = 1024

// ---------------- device scratch (no allocs allowed) ----------------
__device__ unsigned long long g_part2[(size_t)SPLITS*NTOK*En/2]; // 16 MB
__device__ float2 g_gate[NTOK];
__device__ int2   g_eidx[NTOK];

// ---------------- f32x2 helpers ----------------
__device__ __forceinline__ unsigned long long ffma2(unsigned long long a,
                                                    unsigned long long b,
                                                    unsigned long long c) {
    unsigned long long d;
    asm("fma.rn.f32x2 %0, %1, %2, %3;" : "=l"(d) : "l"(a), "l"(b), "l"(c));
    return d;
}
__device__ __forceinline__ unsigned long long pack2(float x) {
    unsigned long long r;
    asm("mov.b64 %0, {%1, %1};" : "=l"(r) : "r"(__float_as_int(x)));
    return r;
}

// ================= K1: zero-fill output + split-K fp32 GEMM =================
__global__ void __launch_bounds__(K1_THREADS)
k1_zero_gemm(const float* __restrict__ x, const float* __restrict__ W,
             float* __restrict__ out, long long out_n)
{
    // ---- phase A: zero the whole output (drains via DRAM while GEMM runs) ----
    {
        long long n4 = out_n >> 2;
        float4 z = make_float4(0.f, 0.f, 0.f, 0.f);
        float4* o4 = (float4*)out;
        long long idx    = (long long)blockIdx.x * K1_THREADS + threadIdx.x;
        long long stride = (long long)gridDim.x * K1_THREADS;
        for (long long i = idx; i < n4; i += stride) o4[i] = z;
        if (blockIdx.x == 0 && threadIdx.x < (int)(out_n & 3LL))
            out[n4*4 + threadIdx.x] = 0.f;
    }

    // ---- phase B: GEMM partial: 64 tokens x 64 experts over D-range 256 ----
    __shared__ float xs[TOKTILE][DC + 1];   // +1 pad => conflict-free
    __shared__ float ws[DC][En];            // rows 256B => aligned LDS.128

    const int ct = blockIdx.x % (NTOK/TOKTILE);
    const int sp = blockIdx.x / (NTOK/TOKTILE);
    const int T0 = ct * TOKTILE;
    const int d0 = sp * DSUB;
    const int tid = threadIdx.x;
    const int tg  = tid >> 3;   // 16 token-groups of 4 tokens
    const int eg  = tid & 7;    // 8 expert-groups of 8 experts (4 f32x2 pairs)

    unsigned long long acc[16];
#pragma unroll
    for (int i = 0; i < 16; ++i) acc[i] = 0ull;

#pragma unroll
    for (int c = 0; c < DSUB/DC; ++c) {
        const int dc0 = d0 + c*DC;
        __syncthreads();
        // fill x tile: coalesced LDG.32, conflict-free STS
#pragma unroll
        for (int i = tid; i < TOKTILE*DC; i += K1_THREADS) {
            int t = i >> 6, d = i & 63;
            xs[t][d] = x[(size_t)(T0 + t)*Dn + dc0 + d];
        }
        // fill W tile
#pragma unroll
        for (int i = tid; i < DC*En; i += K1_THREADS) {
            int d = i >> 6, e = i & 63;
            ws[d][e] = W[(size_t)(dc0 + d)*En + e];
        }
        __syncthreads();

#pragma unroll 4
        for (int d = 0; d < DC; ++d) {
            unsigned long long X0 = pack2(xs[4*tg + 0][d]);
            unsigned long long X1 = pack2(xs[4*tg + 1][d]);
            unsigned long long X2 = pack2(xs[4*tg + 2][d]);
            unsigned long long X3 = pack2(xs[4*tg + 3][d]);
            const ulonglong2* wr = (const ulonglong2*)&ws[d][8*eg];
            ulonglong2 wa = wr[0];
            ulonglong2 wb = wr[1];
            acc[ 0] = ffma2(X0, wa.x, acc[ 0]);
            acc[ 1] = ffma2(X0, wa.y, acc[ 1]);
            acc[ 2] = ffma2(X0, wb.x, acc[ 2]);
            acc[ 3] = ffma2(X0, wb.y, acc[ 3]);
            acc[ 4] = ffma2(X1, wa.x, acc[ 4]);
            acc[ 5] = ffma2(X1, wa.y, acc[ 5]);
            acc[ 6] = ffma2(X1, wb.x, acc[ 6]);
            acc[ 7] = ffma2(X1, wb.y, acc[ 7]);
            acc[ 8] = ffma2(X2, wa.x, acc[ 8]);
            acc[ 9] = ffma2(X2, wa.y, acc[ 9]);
            acc[10] = ffma2(X2, wb.x, acc[10]);
            acc[11] = ffma2(X2, wb.y, acc[11]);
            acc[12] = ffma2(X3, wa.x, acc[12]);
            acc[13] = ffma2(X3, wa.y, acc[13]);
            acc[14] = ffma2(X3, wb.x, acc[14]);
            acc[15] = ffma2(X3, wb.y, acc[15]);
        }
    }

    // store partials (aligned 64-bit stores of expert pairs)
#pragma unroll
    for (int i = 0; i < 4; ++i) {
        int t = T0 + 4*tg + i;
        unsigned long long* dst =
            g_part2 + ((size_t)sp*NTOK + t)*(En/2) + 4*eg;
#pragma unroll
        for (int j = 0; j < 4; ++j) dst[j] = acc[i*4 + j];
    }
}

// ================= K2: reduce partials + softmax + top-2 =================
#define K2_WARPS 8
__global__ void __launch_bounds__(K2_WARPS*32)
k2_softmax_top2(const float* __restrict__ b)
{
    int t    = blockIdx.x * K2_WARPS + (threadIdx.x >> 5);
    int lane = threadIdx.x & 31;
    if (t >= NTOK) return;

    const float* gp = (const float*)g_part2;
    float l0 = 0.f, l1 = 0.f;
#pragma unroll
    for (int s = 0; s < SPLITS; ++s) {
        const float* p = gp + ((size_t)s*NTOK + t)*En;
        l0 += p[lane];
        l1 += p[lane + 32];
    }
    l0 += b[lane];
    l1 += b[lane + 32];

    // softmax (max-subtract, exp, divide)
    float m = fmaxf(l0, l1);
#pragma unroll
    for (int o = 16; o > 0; o >>= 1) m = fmaxf(m, __shfl_xor_sync(0xffffffffu, m, o));
    float p0 = expf(l0 - m), p1 = expf(l1 - m);
    float s = p0 + p1;
#pragma unroll
    for (int o = 16; o > 0; o >>= 1) s += __shfl_xor_sync(0xffffffffu, s, o);
    p0 = p0 / s;
    p1 = p1 / s;

    // top-1 on probs, tie -> lower index
    float bp; int be;
    if (p1 > p0) { bp = p1; be = lane + 32; } else { bp = p0; be = lane; }
    float wp = bp; int we = be;
#pragma unroll
    for (int o = 16; o > 0; o >>= 1) {
        float op = __shfl_xor_sync(0xffffffffu, wp, o);
        int   oe = __shfl_xor_sync(0xffffffffu, we, o);
        if (op > wp || (op == wp && oe < we)) { wp = op; we = oe; }
    }
    // top-2: exclude winner index
    float a0 = (lane      == we) ? -1.f : p0;
    float a1 = (lane + 32 == we) ? -1.f : p1;
    float bp2; int be2;
    if (a1 > a0) { bp2 = a1; be2 = lane + 32; } else { bp2 = a0; be2 = lane; }
    float wp2 = bp2; int we2 = be2;
#pragma unroll
    for (int o = 16; o > 0; o >>= 1) {
        float op = __shfl_xor_sync(0xffffffffu, wp2, o);
        int   oe = __shfl_xor_sync(0xffffffffu, we2, o);
        if (op > wp2 || (op == wp2 && oe < we2)) { wp2 = op; we2 = oe; }
    }

    if (lane == 0) {
        g_gate[t] = make_float2(wp, wp2);
        g_eidx[t] = make_int2(we, we2);
    }
}

// ================= K3: per-(g,k) scan (cumsum positions) + scatter =================
#define K3_THREADS 512
__global__ void __launch_bounds__(K3_THREADS)
k3_scan_scatter(float* __restrict__ out, long long out_n,
                const int* __restrict__ capp, int has_mask)
{
    __shared__ int cnt[8][En];
    __shared__ unsigned char se[NTOK*2];   // expert index per (token, slot)

    int tid = threadIdx.x;
    int cap = 64;
    if (capp) { cap = capp[0]; if (cap > 64) cap = 64; }

    for (int i = tid; i < NTOK; i += K3_THREADS) {
        int2 e = g_eidx[i];
        se[2*i + 0] = (unsigned char)e.x;
        se[2*i + 1] = (unsigned char)e.y;
    }
    for (int i = tid; i < 8*En; i += K3_THREADS) ((int*)cnt)[i] = 0;
    __syncthreads();

    int w = tid >> 5, lane = tid & 31;
    if (w < 8) {
        int g = w >> 1, k = w & 1;
        int* mycnt = cnt[w];

        for (int c = 0; c < Sn/32; ++c) {
            int t = g*Sn + c*32 + lane;
            int e = se[2*t + k];
            unsigned mask = __match_any_sync(0xffffffffu, e);
            int rank = __popc(mask & ((1u << lane) - 1u));
            int base = mycnt[e];
            int pos  = base + rank + 1;
            __syncwarp();
            if (rank == 0) mycnt[e] = base + __popc(mask);
            __syncwarp();
            if (pos < cap) {
                float2 gg = g_gate[t];
                float gate = (k == 0) ? gg.x : gg.y;
                long long off = ((long long)t*En + e)*63 + (pos - 1);
                if (off < out_n) out[off] = gate;
                if (has_mask) {
                    long long moff = NCOMB + off;
                    if (moff < out_n) out[moff] = (gate != 0.f) ? 1.f : 0.f;
                }
            }
        }
    }
}

// ================= launch =================
extern "C" void kernel_launch(void* const* d_in, const int* in_sizes, int n_in,
                              void* d_out, int out_size)
{
    const float* x = (const float*)d_in[0];
    const float* W = (const float*)d_in[1];
    const float* b = (const float*)d_in[2];
    const int* capp = (n_in >= 4) ? (const int*)d_in[3] : nullptr;
    float* out = (float*)d_out;
    long long out_n = (long long)out_size;
    int has_mask = (out_n >= 2LL*NCOMB) ? 1 : 0;

    k1_zero_gemm<<<K1_BLOCKS, K1_THREADS>>>(x, W, out, out_n);
    k2_softmax_top2<<<NTOK/K2_WARPS, K2_WARPS*32>>>(b);
    k3_scan_scatter<<<1, K3_THREADS>>>(out, out_n, capp, has_mask);
}

// round 3
// speedup vs baseline: 1.2374x; 1.0764x over previous
#include <cuda_runtime.h>

// ---------------- problem constants ----------------
#define Gn 4
#define Sn 2048
#define Dn 2048
#define En 64
#define NTOK (Gn*Sn)                 // 8192 tokens
#define NCOMB ((long long)NTOK*En*63)// 33,030,144 combine elements
#define SPLITS 8
#define DSUB (Dn/SPLITS)             // 256
#define DC 32                        // K-chunk per smem stage
#define CHUNKS (DSUB/DC)             // 8
#define TOKTILE 64
#define XPAD 36                      // 144B rows: 16B-aligned for cp.async
#define K1_THREADS 128
#define K1_BLOCKS ((NTOK/TOKTILE)*SPLITS)  // 1024

// ---------------- device scratch ----------------
__device__ unsigned long long g_part2[(size_t)SPLITS*NTOK*En/2]; // 16 MB
__device__ float2 g_gate[NTOK];
__device__ int2   g_eidx[NTOK];

// ---------------- helpers ----------------
__device__ __forceinline__ unsigned long long ffma2(unsigned long long a,
                                                    unsigned long long b,
                                                    unsigned long long c) {
    unsigned long long d;
    asm("fma.rn.f32x2 %0, %1, %2, %3;" : "=l"(d) : "l"(a), "l"(b), "l"(c));
    return d;
}
__device__ __forceinline__ unsigned long long pack2(float x) {
    unsigned long long r;
    asm("mov.b64 %0, {%1, %1};" : "=l"(r) : "r"(__float_as_int(x)));
    return r;
}
__device__ __forceinline__ void cp16(float* smem, const float* g) {
    unsigned s = (unsigned)__cvta_generic_to_shared(smem);
    asm volatile("cp.async.cg.shared.global [%0], [%1], 16;" :: "r"(s), "l"(g));
}

__device__ __forceinline__ void fill_async(float* xsb, float* wsb,
    const float* __restrict__ x, const float* __restrict__ W,
    int T0, int dc0, int tid)
{
    // xs: 64 rows x 32 floats (128B/row = 8 x 16B)
#pragma unroll
    for (int k = 0; k < 4; ++k) {
        int i = tid + k*K1_THREADS;          // 0..511
        int row = i >> 3, seg = i & 7;
        cp16(xsb + row*XPAD + seg*4, x + (size_t)(T0+row)*Dn + dc0 + seg*4);
    }
    // ws: 32 rows(d) x 64 floats (256B/row = 16 x 16B)
#pragma unroll
    for (int k = 0; k < 4; ++k) {
        int i = tid + k*K1_THREADS;
        int row = i >> 4, seg = i & 15;
        cp16(wsb + row*En + seg*4, W + (size_t)(dc0+row)*En + seg*4);
    }
}

// ================= K1: zero-fill output + split-K fp32 GEMM =================
__global__ void __launch_bounds__(K1_THREADS, 5)
k1_zero_gemm(const float* __restrict__ x, const float* __restrict__ W,
             float* __restrict__ out, long long out_n)
{
    // ---- phase A: zero the whole output (drains via DRAM while GEMM runs) ----
    {
        long long n4 = out_n >> 2;
        float4 z = make_float4(0.f, 0.f, 0.f, 0.f);
        float4* o4 = (float4*)out;
        long long idx    = (long long)blockIdx.x * K1_THREADS + threadIdx.x;
        long long stride = (long long)gridDim.x * K1_THREADS;
        for (long long i = idx; i < n4; i += stride) o4[i] = z;
        if (blockIdx.x == 0 && threadIdx.x < (int)(out_n & 3LL))
            out[n4*4 + threadIdx.x] = 0.f;
    }

    // ---- phase B: double-buffered cp.async GEMM partial ----
    __shared__ float xs[2][TOKTILE][XPAD];
    __shared__ float ws[2][DC][En];

    const int ct = blockIdx.x % (NTOK/TOKTILE);
    const int sp = blockIdx.x / (NTOK/TOKTILE);
    const int T0 = ct * TOKTILE;
    const int d0 = sp * DSUB;
    const int tid = threadIdx.x;
    const int tg  = tid >> 3;   // 16 token-groups of 4 tokens
    const int eg  = tid & 7;    // 8 expert-groups of 8 experts

    unsigned long long acc[16];
#pragma unroll
    for (int i = 0; i < 16; ++i) acc[i] = 0ull;

    fill_async(&xs[0][0][0], &ws[0][0][0], x, W, T0, d0, tid);
    asm volatile("cp.async.commit_group;");

    for (int c = 0; c < CHUNKS; ++c) {
        const int cb = c & 1;
        if (c + 1 < CHUNKS) {
            fill_async(&xs[cb^1][0][0], &ws[cb^1][0][0], x, W, T0, d0 + (c+1)*DC, tid);
            asm volatile("cp.async.commit_group;");
            asm volatile("cp.async.wait_group 1;");
        } else {
            asm volatile("cp.async.wait_group 0;");
        }
        __syncthreads();

#pragma unroll 4
        for (int d = 0; d < DC; ++d) {
            unsigned long long X0 = pack2(xs[cb][4*tg + 0][d]);
            unsigned long long X1 = pack2(xs[cb][4*tg + 1][d]);
            unsigned long long X2 = pack2(xs[cb][4*tg + 2][d]);
            unsigned long long X3 = pack2(xs[cb][4*tg + 3][d]);
            const ulonglong2* wr = (const ulonglong2*)&ws[cb][d][8*eg];
            ulonglong2 wa = wr[0];
            ulonglong2 wb = wr[1];
            acc[ 0] = ffma2(X0, wa.x, acc[ 0]);
            acc[ 1] = ffma2(X0, wa.y, acc[ 1]);
            acc[ 2] = ffma2(X0, wb.x, acc[ 2]);
            acc[ 3] = ffma2(X0, wb.y, acc[ 3]);
            acc[ 4] = ffma2(X1, wa.x, acc[ 4]);
            acc[ 5] = ffma2(X1, wa.y, acc[ 5]);
            acc[ 6] = ffma2(X1, wb.x, acc[ 6]);
            acc[ 7] = ffma2(X1, wb.y, acc[ 7]);
            acc[ 8] = ffma2(X2, wa.x, acc[ 8]);
            acc[ 9] = ffma2(X2, wa.y, acc[ 9]);
            acc[10] = ffma2(X2, wb.x, acc[10]);
            acc[11] = ffma2(X2, wb.y, acc[11]);
            acc[12] = ffma2(X3, wa.x, acc[12]);
            acc[13] = ffma2(X3, wa.y, acc[13]);
            acc[14] = ffma2(X3, wb.x, acc[14]);
            acc[15] = ffma2(X3, wb.y, acc[15]);
        }
        __syncthreads();
    }

    // store partials (aligned 64-bit stores of expert pairs)
#pragma unroll
    for (int i = 0; i < 4; ++i) {
        int t = T0 + 4*tg + i;
        unsigned long long* dst =
            g_part2 + ((size_t)sp*NTOK + t)*(En/2) + 4*eg;
#pragma unroll
        for (int j = 0; j < 4; ++j) dst[j] = acc[i*4 + j];
    }
}

// ================= K2: reduce partials + softmax + top-2 =================
#define K2_WARPS 8
__global__ void __launch_bounds__(K2_WARPS*32)
k2_softmax_top2(const float* __restrict__ b)
{
    int t    = blockIdx.x * K2_WARPS + (threadIdx.x >> 5);
    int lane = threadIdx.x & 31;
    if (t >= NTOK) return;

    // lane owns experts e0=2*lane, e1=2*lane+1 (pairs are contiguous in g_part2)
    const float2* gp2 = (const float2*)g_part2;
    float l0 = 0.f, l1 = 0.f;
#pragma unroll
    for (int s = 0; s < SPLITS; ++s) {
        float2 v = gp2[((size_t)s*NTOK + t)*(En/2) + lane];
        l0 += v.x; l1 += v.y;
    }
    float2 bb = ((const float2*)b)[lane];
    l0 += bb.x; l1 += bb.y;
    const int e0 = 2*lane, e1 = 2*lane + 1;

    // softmax
    float m = fmaxf(l0, l1);
#pragma unroll
    for (int o = 16; o > 0; o >>= 1) m = fmaxf(m, __shfl_xor_sync(0xffffffffu, m, o));
    float p0 = expf(l0 - m), p1 = expf(l1 - m);
    float s = p0 + p1;
#pragma unroll
    for (int o = 16; o > 0; o >>= 1) s += __shfl_xor_sync(0xffffffffu, s, o);
    p0 = p0 / s;
    p1 = p1 / s;

    // top-1 on probs, tie -> lower index
    float wp; int we;
    if (p1 > p0) { wp = p1; we = e1; } else { wp = p0; we = e0; }
#pragma unroll
    for (int o = 16; o > 0; o >>= 1) {
        float op = __shfl_xor_sync(0xffffffffu, wp, o);
        int   oe = __shfl_xor_sync(0xffffffffu, we, o);
        if (op > wp || (op == wp && oe < we)) { wp = op; we = oe; }
    }
    // top-2: exclude winner index
    float a0 = (e0 == we) ? -1.f : p0;
    float a1 = (e1 == we) ? -1.f : p1;
    float wp2; int we2;
    if (a1 > a0) { wp2 = a1; we2 = e1; } else { wp2 = a0; we2 = e0; }
#pragma unroll
    for (int o = 16; o > 0; o >>= 1) {
        float op = __shfl_xor_sync(0xffffffffu, wp2, o);
        int   oe = __shfl_xor_sync(0xffffffffu, we2, o);
        if (op > wp2 || (op == wp2 && oe < we2)) { wp2 = op; we2 = oe; }
    }

    if (lane == 0) {
        g_gate[t] = make_float2(wp, wp2);
        g_eidx[t] = make_int2(we, we2);
    }
}

// ================= K3: per-(g,k) scan (cumsum positions) + scatter =================
#define K3_THREADS 512
__global__ void __launch_bounds__(K3_THREADS)
k3_scan_scatter(float* __restrict__ out, long long out_n,
                const int* __restrict__ capp, int has_mask)
{
    __shared__ int cnt[8][En];
    __shared__ unsigned char se[NTOK*2];

    int tid = threadIdx.x;
    int cap = 64;
    if (capp) { cap = capp[0]; if (cap > 64) cap = 64; }

    for (int i = tid; i < NTOK; i += K3_THREADS) {
        int2 e = g_eidx[i];
        se[2*i + 0] = (unsigned char)e.x;
        se[2*i + 1] = (unsigned char)e.y;
    }
    for (int i = tid; i < 8*En; i += K3_THREADS) ((int*)cnt)[i] = 0;
    __syncthreads();

    int w = tid >> 5, lane = tid & 31;
    if (w < 8) {
        int g = w >> 1, k = w & 1;
        int* mycnt = cnt[w];

        for (int c = 0; c < Sn/32; ++c) {
            int t = g*Sn + c*32 + lane;
            int e = se[2*t + k];
            unsigned mask = __match_any_sync(0xffffffffu, e);
            int rank = __popc(mask & ((1u << lane) - 1u));
            int base = mycnt[e];
            int pos  = base + rank + 1;
            __syncwarp();
            if (rank == 0) mycnt[e] = base + __popc(mask);
            __syncwarp();
            if (pos < cap) {
                float2 gg = g_gate[t];
                float gate = (k == 0) ? gg.x : gg.y;
                long long off = ((long long)t*En + e)*63 + (pos - 1);
                if (off < out_n) out[off] = gate;
                if (has_mask) {
                    long long moff = NCOMB + off;
                    if (moff < out_n) out[moff] = (gate != 0.f) ? 1.f : 0.f;
                }
            }
        }
    }
}

// ================= launch =================
extern "C" void kernel_launch(void* const* d_in, const int* in_sizes, int n_in,
                              void* d_out, int out_size)
{
    const float* x = (const float*)d_in[0];
    const float* W = (const float*)d_in[1];
    const float* b = (const float*)d_in[2];
    const int* capp = (n_in >= 4) ? (const int*)d_in[3] : nullptr;
    float* out = (float*)d_out;
    long long out_n = (long long)out_size;
    int has_mask = (out_n >= 2LL*NCOMB) ? 1 : 0;

    k1_zero_gemm<<<K1_BLOCKS, K1_THREADS>>>(x, W, out, out_n);
    k2_softmax_top2<<<NTOK/K2_WARPS, K2_WARPS*32>>>(b);
    k3_scan_scatter<<<1, K3_THREADS>>>(out, out_n, capp, has_mask);
}

// round 4
// speedup vs baseline: 1.7987x; 1.4536x over previous
#include <cuda_runtime.h>
#include <cuda_bf16.h>

// ---------------- problem constants ----------------
#define Gn 4
#define Sn 2048
#define Dn 2048
#define En 64
#define NTOK (Gn*Sn)                  // 8192 tokens
#define NCOMB ((long long)NTOK*En*63) // 33,030,144 combine elements
#define MCTA 64
#define KC 64
#define NCHUNK (Dn/KC)                // 32
#define K1_THREADS 256
#define K1_BLOCKS (NTOK/MCTA)         // 128

// ---------------- device scratch ----------------
__device__ float  g_logit[(size_t)NTOK*En];   // 2 MB exact fp32 logits (no bias)
__device__ float2 g_gate[NTOK];
__device__ int2   g_eidx[NTOK];

// swizzled byte offset inside a 64x64-bf16 tile (128B rows, XOR-16B swizzle)
__device__ __forceinline__ unsigned swz(int row, int chunk) {
    return (unsigned)(row*128 + ((chunk ^ (row & 7)) << 4));
}

#define LDSM4(R0_,R1_,R2_,R3_,ADDR) \
  asm volatile("ldmatrix.sync.aligned.m8n8.x4.shared.b16 {%0,%1,%2,%3}, [%4];" \
    : "=r"(R0_),"=r"(R1_),"=r"(R2_),"=r"(R3_) : "r"(ADDR))
#define LDSM4T(R0_,R1_,R2_,R3_,ADDR) \
  asm volatile("ldmatrix.sync.aligned.m8n8.x4.trans.shared.b16 {%0,%1,%2,%3}, [%4];" \
    : "=r"(R0_),"=r"(R1_),"=r"(R2_),"=r"(R3_) : "r"(ADDR))
#define HMMA(C_,A0,A1,A2,A3,B0,B1) \
  asm volatile("mma.sync.aligned.m16n8k16.row.col.f32.bf16.bf16.f32 " \
    "{%0,%1,%2,%3}, {%4,%5,%6,%7}, {%8,%9}, {%0,%1,%2,%3};" \
    : "+f"(C_[0]),"+f"(C_[1]),"+f"(C_[2]),"+f"(C_[3]) \
    : "r"(A0),"r"(A1),"r"(A2),"r"(A3),"r"(B0),"r"(B1))

// ================= K1: zero-fill output + bf16-split tensor-core GEMM ========
__global__ void __launch_bounds__(K1_THREADS)
k1_zero_gemm(const float* __restrict__ x, const float* __restrict__ W,
             float* __restrict__ out, long long out_n)
{
    // ---- phase A: zero the whole output (drains via DRAM while GEMM runs) ----
    {
        long long n4 = out_n >> 2;
        float4 z = make_float4(0.f, 0.f, 0.f, 0.f);
        float4* o4 = (float4*)out;
        for (long long i = (long long)blockIdx.x*K1_THREADS + threadIdx.x; i < n4;
             i += (long long)gridDim.x*K1_THREADS) o4[i] = z;
        if (blockIdx.x == 0 && threadIdx.x < (int)(out_n & 3LL))
            out[n4*4 + threadIdx.x] = 0.f;
    }

    // ---- phase B: 64 tokens x 64 experts, full K=2048, bf16 split (hh+hl+lh) ----
    __shared__ __align__(16) unsigned char sm[32768];
    const unsigned sb = (unsigned)__cvta_generic_to_shared(sm);
    const unsigned XH = 0, XL = 8192, WHs = 16384, WLs = 24576;

    const int tid  = threadIdx.x;
    const int T0   = blockIdx.x * MCTA;
    const int lane = tid & 31, w = tid >> 5;
    const int R0 = (w & 3) * 16;     // 16 token rows per warp
    const int C0 = (w >> 2) * 32;    // 32 experts per warp

    float acc[4][4];
#pragma unroll
    for (int i = 0; i < 4; ++i)
#pragma unroll
        for (int j = 0; j < 4; ++j) acc[i][j] = 0.f;

    // prefetch chunk 0 (each thread: 8 float2 of x, 8 float2 of W; coalesced)
    float2 xv[8], wv[8];
#pragma unroll
    for (int i = 0; i < 8; ++i) {
        int idx = tid + K1_THREADS*i;
        int row = idx >> 5, p = idx & 31;
        xv[i] = *(const float2*)(x + (size_t)(T0 + row)*Dn + 2*p);
        wv[i] = *(const float2*)(W + (size_t)row*En + 2*p);
    }

    // per-lane ldmatrix geometry
    const int lm = lane >> 3;                 // matrix id 0..3
    const int lr = lane & 7;                  // row within matrix
    const int arow = R0 + ((lm & 1) << 3) + lr;
    const int half = lm >> 1;                 // chunk offset 0/1

    for (int c = 0; c < NCHUNK; ++c) {
        __syncthreads();                      // bf16 tiles free (prev mma done)
        // convert + swizzled STS (conflict-free: 32 lanes fill one 128B row)
#pragma unroll
        for (int i = 0; i < 8; ++i) {
            int idx = tid + K1_THREADS*i;
            int row = idx >> 5, p = idx & 31;
            unsigned off = swz(row, p >> 2) + ((p & 3) << 2);
            __nv_bfloat162 h, l;
            h.x = __float2bfloat16(xv[i].x);
            h.y = __float2bfloat16(xv[i].y);
            l.x = __float2bfloat16(xv[i].x - __bfloat162float(h.x));
            l.y = __float2bfloat16(xv[i].y - __bfloat162float(h.y));
            *(__nv_bfloat162*)(sm + XH + off) = h;
            *(__nv_bfloat162*)(sm + XL + off) = l;
            h.x = __float2bfloat16(wv[i].x);
            h.y = __float2bfloat16(wv[i].y);
            l.x = __float2bfloat16(wv[i].x - __bfloat162float(h.x));
            l.y = __float2bfloat16(wv[i].y - __bfloat162float(h.y));
            *(__nv_bfloat162*)(sm + WHs + off) = h;
            *(__nv_bfloat162*)(sm + WLs + off) = l;
        }
        if (c + 1 < NCHUNK) {                 // issue next LDG; hides behind mma
            const int dc0 = (c + 1)*KC;
#pragma unroll
            for (int i = 0; i < 8; ++i) {
                int idx = tid + K1_THREADS*i;
                int row = idx >> 5, p = idx & 31;
                xv[i] = *(const float2*)(x + (size_t)(T0 + row)*Dn + dc0 + 2*p);
                wv[i] = *(const float2*)(W + (size_t)(dc0 + row)*En + 2*p);
            }
        }
        __syncthreads();                      // bf16 tiles ready

#pragma unroll
        for (int ks = 0; ks < 4; ++ks) {
            unsigned ah0,ah1,ah2,ah3, al0,al1,al2,al3;
            const unsigned aoff = swz(arow, 2*ks + half);
            LDSM4(ah0,ah1,ah2,ah3, sb + XH + aoff);
            LDSM4(al0,al1,al2,al3, sb + XL + aoff);
            const int krow = 16*ks + ((lm & 1) << 3) + lr;
            unsigned bh[8], bl[8];
            const unsigned boff0 = swz(krow, (C0 >> 3) + half);
            const unsigned boff1 = swz(krow, (C0 >> 3) + 2 + half);
            LDSM4T(bh[0],bh[1],bh[2],bh[3], sb + WHs + boff0);
            LDSM4T(bh[4],bh[5],bh[6],bh[7], sb + WHs + boff1);
            LDSM4T(bl[0],bl[1],bl[2],bl[3], sb + WLs + boff0);
            LDSM4T(bl[4],bl[5],bl[6],bl[7], sb + WLs + boff1);
#pragma unroll
            for (int nt = 0; nt < 4; ++nt) {
                HMMA(acc[nt], ah0,ah1,ah2,ah3, bh[2*nt], bh[2*nt+1]);
                HMMA(acc[nt], ah0,ah1,ah2,ah3, bl[2*nt], bl[2*nt+1]);
                HMMA(acc[nt], al0,al1,al2,al3, bh[2*nt], bh[2*nt+1]);
            }
        }
    }

    // epilogue: exact fp32 logits to gmem
    const int g = lane >> 2, cc = (lane & 3)*2;
    const int t0 = T0 + R0 + g;
#pragma unroll
    for (int nt = 0; nt < 4; ++nt) {
        int e = C0 + nt*8 + cc;
        *(float2*)&g_logit[(size_t)t0*En + e]       = make_float2(acc[nt][0], acc[nt][1]);
        *(float2*)&g_logit[(size_t)(t0+8)*En + e]   = make_float2(acc[nt][2], acc[nt][3]);
    }
}

// ================= K2: bias + softmax + top-2 (warp per token) ===============
#define K2_WARPS 8
__global__ void __launch_bounds__(K2_WARPS*32)
k2_softmax_top2(const float* __restrict__ b)
{
    int t    = blockIdx.x * K2_WARPS + (threadIdx.x >> 5);
    int lane = threadIdx.x & 31;
    if (t >= NTOK) return;

    float2 v  = ((const float2*)g_logit)[(size_t)t*32 + lane];
    float2 bb = ((const float2*)b)[lane];
    float l0 = v.x + bb.x, l1 = v.y + bb.y;
    const int e0 = 2*lane, e1 = 2*lane + 1;

    float m = fmaxf(l0, l1);
#pragma unroll
    for (int o = 16; o > 0; o >>= 1) m = fmaxf(m, __shfl_xor_sync(0xffffffffu, m, o));
    float p0 = expf(l0 - m), p1 = expf(l1 - m);
    float s = p0 + p1;
#pragma unroll
    for (int o = 16; o > 0; o >>= 1) s += __shfl_xor_sync(0xffffffffu, s, o);
    p0 = p0 / s;
    p1 = p1 / s;

    float wp; int we;
    if (p1 > p0) { wp = p1; we = e1; } else { wp = p0; we = e0; }
#pragma unroll
    for (int o = 16; o > 0; o >>= 1) {
        float op = __shfl_xor_sync(0xffffffffu, wp, o);
        int   oe = __shfl_xor_sync(0xffffffffu, we, o);
        if (op > wp || (op == wp && oe < we)) { wp = op; we = oe; }
    }
    float a0 = (e0 == we) ? -1.f : p0;
    float a1 = (e1 == we) ? -1.f : p1;
    float wp2; int we2;
    if (a1 > a0) { wp2 = a1; we2 = e1; } else { wp2 = a0; we2 = e0; }
#pragma unroll
    for (int o = 16; o > 0; o >>= 1) {
        float op = __shfl_xor_sync(0xffffffffu, wp2, o);
        int   oe = __shfl_xor_sync(0xffffffffu, we2, o);
        if (op > wp2 || (op == wp2 && oe < we2)) { wp2 = op; we2 = oe; }
    }

    if (lane == 0) {
        g_gate[t] = make_float2(wp, wp2);
        g_eidx[t] = make_int2(we, we2);
    }
}

// ========== K3: 8 CTAs, one per (group,slot): scan positions + scatter =======
__global__ void __launch_bounds__(256)
k3_scan_scatter(float* __restrict__ out, long long out_n,
                const int* __restrict__ capp, int has_mask)
{
    __shared__ float gate_s[Sn];
    __shared__ unsigned char e_s[Sn];
    __shared__ int cnt[En];

    const int g = blockIdx.x >> 1, k = blockIdx.x & 1;
    const int tid = threadIdx.x;
    int cap = 64;
    if (capp) { cap = capp[0]; if (cap > 64) cap = 64; }

    for (int i = tid; i < Sn; i += 256) {
        int2   e  = g_eidx[g*Sn + i];
        float2 gg = g_gate[g*Sn + i];
        e_s[i]    = (unsigned char)(k ? e.y : e.x);
        gate_s[i] = k ? gg.y : gg.x;
    }
    for (int i = tid; i < En; i += 256) cnt[i] = 0;
    __syncthreads();

    if (tid < 32) {
        const int lane = tid;
        for (int c = 0; c < Sn/32; ++c) {
            int s = c*32 + lane;
            int e = e_s[s];
            unsigned mask = __match_any_sync(0xffffffffu, e);
            int rank = __popc(mask & ((1u << lane) - 1u));
            int base = cnt[e];
            int pos  = base + rank + 1;
            __syncwarp();
            if (rank == 0) cnt[e] = base + __popc(mask);
            __syncwarp();
            if (pos < cap) {
                float gate = gate_s[s];
                long long t   = (long long)(g*Sn + s);
                long long off = (t*En + e)*63 + (pos - 1);
                if (off < out_n) out[off] = gate;
                if (has_mask) {
                    long long moff = NCOMB + off;
                    if (moff < out_n) out[moff] = (gate != 0.f) ? 1.f : 0.f;
                }
            }
        }
    }
}

// ================= launch =================
extern "C" void kernel_launch(void* const* d_in, const int* in_sizes, int n_in,
                              void* d_out, int out_size)
{
    const float* x = (const float*)d_in[0];
    const float* W = (const float*)d_in[1];
    const float* b = (const float*)d_in[2];
    const int* capp = (n_in >= 4) ? (const int*)d_in[3] : nullptr;
    float* out = (float*)d_out;
    long long out_n = (long long)out_size;
    int has_mask = (out_n >= 2LL*NCOMB) ? 1 : 0;

    k1_zero_gemm<<<K1_BLOCKS, K1_THREADS>>>(x, W, out, out_n);
    k2_softmax_top2<<<NTOK/K2_WARPS, K2_WARPS*32>>>(b);
    k3_scan_scatter<<<8, 256>>>(out, out_n, capp, has_mask);
}

// round 5
// speedup vs baseline: 2.4441x; 1.3588x over previous
#include <cuda_runtime.h>
#include <cuda_bf16.h>

// ---------------- problem constants ----------------
#define Gn 4
#define Sn 2048
#define Dn 2048
#define En 64
#define NTOK (Gn*Sn)                  // 8192 tokens
#define NCOMB ((long long)NTOK*En*63) // 33,030,144 combine elements
#define MCTA 64
#define KC 64
#define NCHUNK (Dn/KC)                // 32
#define K1_THREADS 256
#define K1_BLOCKS (NTOK/MCTA)         // 128
#define ZPC 16                        // zero-fill float4 stores per thread per chunk

// ---------------- device scratch ----------------
__device__ float2 g_gate[NTOK];
__device__ int2   g_eidx[NTOK];

// swizzled byte offset inside a 64x64-bf16 tile (128B rows, XOR-16B swizzle)
__device__ __forceinline__ unsigned swz(int row, int chunk) {
    return (unsigned)(row*128 + ((chunk ^ (row & 7)) << 4));
}

#define LDSM4(R0_,R1_,R2_,R3_,ADDR) \
  asm volatile("ldmatrix.sync.aligned.m8n8.x4.shared.b16 {%0,%1,%2,%3}, [%4];" \
    : "=r"(R0_),"=r"(R1_),"=r"(R2_),"=r"(R3_) : "r"(ADDR))
#define LDSM4T(R0_,R1_,R2_,R3_,ADDR) \
  asm volatile("ldmatrix.sync.aligned.m8n8.x4.trans.shared.b16 {%0,%1,%2,%3}, [%4];" \
    : "=r"(R0_),"=r"(R1_),"=r"(R2_),"=r"(R3_) : "r"(ADDR))
#define HMMA(C_,A0,A1,A2,A3,B0,B1) \
  asm volatile("mma.sync.aligned.m16n8k16.row.col.f32.bf16.bf16.f32 " \
    "{%0,%1,%2,%3}, {%4,%5,%6,%7}, {%8,%9}, {%0,%1,%2,%3};" \
    : "+f"(C_[0]),"+f"(C_[1]),"+f"(C_[2]),"+f"(C_[3]) \
    : "r"(A0),"r"(A1),"r"(A2),"r"(A3),"r"(B0),"r"(B1))

// ===== K1: interleaved zero-fill + bf16-split tensor GEMM + fused softmax/top2 =====
__global__ void __launch_bounds__(K1_THREADS)
k1_fused(const float* __restrict__ x, const float* __restrict__ W,
         const float* __restrict__ b, float* __restrict__ out, long long out_n)
{
    __shared__ __align__(16) unsigned char sm[32768];
    const unsigned sb = (unsigned)__cvta_generic_to_shared(sm);
    const unsigned XH = 0, XL = 8192, WHs = 16384, WLs = 24576;

    const int tid  = threadIdx.x;
    const int T0   = blockIdx.x * MCTA;
    const int lane = tid & 31, w = tid >> 5;
    const int R0 = (w & 3) * 16;     // 16 token rows per warp
    const int C0 = (w >> 2) * 32;    // 32 experts per warp

    // zero-fill bookkeeping
    const long long n4 = out_n >> 2;
    const long long zbase = (long long)blockIdx.x*K1_THREADS + tid;
    const long long zstr  = (long long)K1_BLOCKS*K1_THREADS;
    float4* o4 = (float4*)out;
    const float4 zz = make_float4(0.f, 0.f, 0.f, 0.f);
    if (blockIdx.x == 0 && tid < (int)(out_n & 3LL)) out[n4*4 + tid] = 0.f;

    float acc[4][4];
#pragma unroll
    for (int i = 0; i < 4; ++i)
#pragma unroll
        for (int j = 0; j < 4; ++j) acc[i][j] = 0.f;

    // prefetch chunk 0
    float2 xv[8], wv[8];
#pragma unroll
    for (int i = 0; i < 8; ++i) {
        int idx = tid + K1_THREADS*i;
        int row = idx >> 5, p = idx & 31;
        xv[i] = *(const float2*)(x + (size_t)(T0 + row)*Dn + 2*p);
        wv[i] = *(const float2*)(W + (size_t)row*En + 2*p);
    }

    const int lm = lane >> 3;
    const int lr = lane & 7;
    const int arow = R0 + ((lm & 1) << 3) + lr;
    const int half = lm >> 1;

    for (int c = 0; c < NCHUNK; ++c) {
        __syncthreads();                      // tiles free
#pragma unroll
        for (int i = 0; i < 8; ++i) {
            int idx = tid + K1_THREADS*i;
            int row = idx >> 5, p = idx & 31;
            unsigned off = swz(row, p >> 2) + ((p & 3) << 2);
            __nv_bfloat162 h, l;
            h.x = __float2bfloat16(xv[i].x);
            h.y = __float2bfloat16(xv[i].y);
            l.x = __float2bfloat16(xv[i].x - __bfloat162float(h.x));
            l.y = __float2bfloat16(xv[i].y - __bfloat162float(h.y));
            *(__nv_bfloat162*)(sm + XH + off) = h;
            *(__nv_bfloat162*)(sm + XL + off) = l;
            h.x = __float2bfloat16(wv[i].x);
            h.y = __float2bfloat16(wv[i].y);
            l.x = __float2bfloat16(wv[i].x - __bfloat162float(h.x));
            l.y = __float2bfloat16(wv[i].y - __bfloat162float(h.y));
            *(__nv_bfloat162*)(sm + WHs + off) = h;
            *(__nv_bfloat162*)(sm + WLs + off) = l;
        }
        if (c + 1 < NCHUNK) {
            const int dc0 = (c + 1)*KC;
#pragma unroll
            for (int i = 0; i < 8; ++i) {
                int idx = tid + K1_THREADS*i;
                int row = idx >> 5, p = idx & 31;
                xv[i] = *(const float2*)(x + (size_t)(T0 + row)*Dn + dc0 + 2*p);
                wv[i] = *(const float2*)(W + (size_t)(dc0 + row)*En + 2*p);
            }
        }
        // interleaved zero-fill batch: drains via DRAM while mma below runs
#pragma unroll
        for (int j = 0; j < ZPC; ++j) {
            long long zi = zbase + (long long)(c*ZPC + j)*zstr;
            if (zi < n4) o4[zi] = zz;
        }
        __syncthreads();                      // tiles ready

#pragma unroll
        for (int ks = 0; ks < 4; ++ks) {
            unsigned ah0,ah1,ah2,ah3, al0,al1,al2,al3;
            const unsigned aoff = swz(arow, 2*ks + half);
            LDSM4(ah0,ah1,ah2,ah3, sb + XH + aoff);
            LDSM4(al0,al1,al2,al3, sb + XL + aoff);
            const int krow = 16*ks + ((lm & 1) << 3) + lr;
            unsigned bh[8], bl[8];
            const unsigned boff0 = swz(krow, (C0 >> 3) + half);
            const unsigned boff1 = swz(krow, (C0 >> 3) + 2 + half);
            LDSM4T(bh[0],bh[1],bh[2],bh[3], sb + WHs + boff0);
            LDSM4T(bh[4],bh[5],bh[6],bh[7], sb + WHs + boff1);
            LDSM4T(bl[0],bl[1],bl[2],bl[3], sb + WLs + boff0);
            LDSM4T(bl[4],bl[5],bl[6],bl[7], sb + WLs + boff1);
#pragma unroll
            for (int nt = 0; nt < 4; ++nt) {
                HMMA(acc[nt], ah0,ah1,ah2,ah3, bh[2*nt], bh[2*nt+1]);
                HMMA(acc[nt], ah0,ah1,ah2,ah3, bl[2*nt], bl[2*nt+1]);
                HMMA(acc[nt], al0,al1,al2,al3, bh[2*nt], bh[2*nt+1]);
            }
        }
    }

    // ---- fused epilogue: accs -> smem logits -> softmax + top2 per token ----
    __syncthreads();                          // all tile reads done; reuse sm
    float* lg = (float*)sm;                   // [64][64]
    {
        const int g = lane >> 2, cc = (lane & 3)*2;
#pragma unroll
        for (int nt = 0; nt < 4; ++nt) {
            int e = C0 + nt*8 + cc;
            lg[(R0 + g)*En + e]     = acc[nt][0];
            lg[(R0 + g)*En + e + 1] = acc[nt][1];
            lg[(R0 + g + 8)*En + e]     = acc[nt][2];
            lg[(R0 + g + 8)*En + e + 1] = acc[nt][3];
        }
    }
    __syncthreads();

    {
        float2 bb = ((const float2*)b)[lane];
        const int e0 = 2*lane, e1 = 2*lane + 1;
        for (int r = w*8; r < w*8 + 8; ++r) {
            float2 v = *(float2*)&lg[r*En + 2*lane];
            float l0 = v.x + bb.x, l1 = v.y + bb.y;

            float m = fmaxf(l0, l1);
#pragma unroll
            for (int o = 16; o > 0; o >>= 1) m = fmaxf(m, __shfl_xor_sync(0xffffffffu, m, o));
            float p0 = expf(l0 - m), p1 = expf(l1 - m);
            float s = p0 + p1;
#pragma unroll
            for (int o = 16; o > 0; o >>= 1) s += __shfl_xor_sync(0xffffffffu, s, o);
            p0 = p0 / s;
            p1 = p1 / s;

            float wp; int we;
            if (p1 > p0) { wp = p1; we = e1; } else { wp = p0; we = e0; }
#pragma unroll
            for (int o = 16; o > 0; o >>= 1) {
                float op = __shfl_xor_sync(0xffffffffu, wp, o);
                int   oe = __shfl_xor_sync(0xffffffffu, we, o);
                if (op > wp || (op == wp && oe < we)) { wp = op; we = oe; }
            }
            float a0 = (e0 == we) ? -1.f : p0;
            float a1 = (e1 == we) ? -1.f : p1;
            float wp2; int we2;
            if (a1 > a0) { wp2 = a1; we2 = e1; } else { wp2 = a0; we2 = e0; }
#pragma unroll
            for (int o = 16; o > 0; o >>= 1) {
                float op = __shfl_xor_sync(0xffffffffu, wp2, o);
                int   oe = __shfl_xor_sync(0xffffffffu, we2, o);
                if (op > wp2 || (op == wp2 && oe < we2)) { wp2 = op; we2 = oe; }
            }
            if (lane == 0) {
                g_gate[T0 + r] = make_float2(wp, wp2);
                g_eidx[T0 + r] = make_int2(we, we2);
            }
        }
    }
}

// ===== K3: 8 CTAs x 8 warps: hierarchical scan (match + warp-prefix) + scatter =====
__global__ void __launch_bounds__(256)
k3_scan_scatter(float* __restrict__ out, long long out_n,
                const int* __restrict__ capp, int has_mask)
{
    __shared__ float gate_s[Sn];
    __shared__ unsigned char e_s[Sn];
    __shared__ unsigned short pl[Sn];    // warp-local 0-indexed position
    __shared__ int cnt[8][En];
    __shared__ int basew[8][En];

    const int g = blockIdx.x >> 1, k = blockIdx.x & 1;
    const int tid = threadIdx.x;
    const int w = tid >> 5, lane = tid & 31;
    int cap = 64;
    if (capp) { cap = capp[0]; if (cap > 64) cap = 64; }

    for (int i = tid; i < Sn; i += 256) {
        int2   e  = g_eidx[g*Sn + i];
        float2 gg = g_gate[g*Sn + i];
        e_s[i]    = (unsigned char)(k ? e.y : e.x);
        gate_s[i] = k ? gg.y : gg.x;
    }
    for (int i = tid; i < 8*En; i += 256) ((int*)cnt)[i] = 0;
    __syncthreads();

    // pass 1: per-warp local ranks over its 256 tokens
    int* mycnt = cnt[w];
    for (int c = 0; c < 8; ++c) {
        int s = w*256 + c*32 + lane;
        int e = e_s[s];
        unsigned mask = __match_any_sync(0xffffffffu, e);
        int rank = __popc(mask & ((1u << lane) - 1u));
        int base = mycnt[e];
        pl[s] = (unsigned short)(base + rank);
        __syncwarp();
        if (rank == 0) mycnt[e] = base + __popc(mask);
        __syncwarp();
    }
    __syncthreads();

    // warp-exclusive prefix per expert
    if (tid < En) {
        int a = 0;
#pragma unroll
        for (int ww = 0; ww < 8; ++ww) { basew[ww][tid] = a; a += cnt[ww][tid]; }
    }
    __syncthreads();

    // pass 2: scatter with global positions
    for (int c = 0; c < 8; ++c) {
        int s = w*256 + c*32 + lane;
        int e = e_s[s];
        int pos0 = basew[w][e] + (int)pl[s];         // 0-indexed
        if (pos0 + 1 < cap) {
            float gate = gate_s[s];
            long long t   = (long long)(g*Sn + s);
            long long off = (t*En + e)*63 + pos0;
            if (off < out_n) out[off] = gate;
            if (has_mask) {
                long long moff = NCOMB + off;
                if (moff < out_n) out[moff] = (gate != 0.f) ? 1.f : 0.f;
            }
        }
    }
}

// ================= launch =================
extern "C" void kernel_launch(void* const* d_in, const int* in_sizes, int n_in,
                              void* d_out, int out_size)
{
    const float* x = (const float*)d_in[0];
    const float* W = (const float*)d_in[1];
    const float* b = (const float*)d_in[2];
    const int* capp = (n_in >= 4) ? (const int*)d_in[3] : nullptr;
    float* out = (float*)d_out;
    long long out_n = (long long)out_size;
    int has_mask = (out_n >= 2LL*NCOMB) ? 1 : 0;

    k1_fused<<<K1_BLOCKS, K1_THREADS>>>(x, W, b, out, out_n);
    k3_scan_scatter<<<8, 256>>>(out, out_n, capp, has_mask);
}